// round 7
// baseline (speedup 1.0000x reference)
#include <cuda_runtime.h>
#include <math.h>

// GridPooling: points [B,N,3] f32, features [B,N,F] f32 -> grid [B,32,32,32,F] f32
// B=4, N=100000, F=64, GRID=32.
// Counting-sort point ids by (batch,voxel), then per-voxel gather-max with zero
// output atomics. 5 kernels (init & scan_sums eliminated via static init +
// self-resetting state + atomic block-base). Gather: 4-way sub-split per warp,
// 8-pt unroll (16 loads in flight per thread).
#define GRIDR   32
#define NVOX    (GRIDR * GRIDR * GRIDR)   // 32768
#define NBATCH  4
#define NBINS   (NBATCH * NVOX)           // 131072
#define FDIM    64
#define MAXPTS  400000

// Persistent state. Statically initialized; each kernel_launch call leaves it
// back in this exact state (g_cnt zeroed by gather, seeds/cursor reset by
// scatter_ids after their consumers ran) -> deterministic across graph replays.
__device__ int g_min_bits = 0x7f800000;   // +INF
__device__ int g_max_bits = 0xff800000;   // -INF
__device__ int g_cursor   = 0;            // plist allocation cursor
__device__ int g_cnt[NBINS];              // zero-init, re-zeroed by gather
__device__ int g_gidx[MAXPTS];            // bin id (b*32768+vox), -1 if OOB
__device__ int g_rank[MAXPTS];            // rank within bin
__device__ int g_plist[MAXPTS];           // point ids grouped by bin
__device__ int g_partoff[NBINS];          // exclusive offset within 256-bin block
__device__ int g_blockbase[NBINS / 256];  // 512 block bases (atomic-allocated)

__device__ __forceinline__ void atomicMinF(int* addr, float v) {
    if (v >= 0.0f) atomicMin(addr, __float_as_int(v));
    else           atomicMax((unsigned int*)addr, __float_as_uint(v));
}
__device__ __forceinline__ void atomicMaxF(int* addr, float v) {
    if (v >= 0.0f) atomicMax(addr, __float_as_int(v));
    else           atomicMin((unsigned int*)addr, __float_as_uint(v));
}
__device__ __forceinline__ void fmax4(float4& a, const float4& b) {
    a.x = fmaxf(a.x, b.x); a.y = fmaxf(a.y, b.y);
    a.z = fmaxf(a.z, b.z); a.w = fmaxf(a.w, b.w);
}

// K0: global min/max over all point coordinates (float4 vectorized).
__global__ void minmax_kernel(const float4* __restrict__ pts, int n4) {
    float lmin =  INFINITY;
    float lmax = -INFINITY;
    int stride = gridDim.x * blockDim.x;
    for (int i = blockIdx.x * blockDim.x + threadIdx.x; i < n4; i += stride) {
        float4 v = pts[i];
        lmin = fminf(lmin, fminf(fminf(v.x, v.y), fminf(v.z, v.w)));
        lmax = fmaxf(lmax, fmaxf(fmaxf(v.x, v.y), fmaxf(v.z, v.w)));
    }
    #pragma unroll
    for (int o = 16; o > 0; o >>= 1) {
        lmin = fminf(lmin, __shfl_xor_sync(0xFFFFFFFFu, lmin, o));
        lmax = fmaxf(lmax, __shfl_xor_sync(0xFFFFFFFFu, lmax, o));
    }
    if ((threadIdx.x & 31) == 0) {
        atomicMinF(&g_min_bits, lmin);
        atomicMaxF(&g_max_bits, lmax);
    }
}

// K1: per-point bin index (exact reference arithmetic) + histogram rank.
__global__ void gidx_kernel(const float* __restrict__ pts, int np, int npb) {
    int p = blockIdx.x * blockDim.x + threadIdx.x;
    if (p >= np) return;
    float pmin  = __int_as_float(g_min_bits);
    float pmax  = __int_as_float(g_max_bits);
    float denom = (pmax - pmin) + 1e-6f;

    float x = pts[p * 3 + 0];
    float y = pts[p * 3 + 1];
    float z = pts[p * 3 + 2];
    int vx = (int)floorf(((x - pmin) / denom) * 32.0f);
    int vy = (int)floorf(((y - pmin) / denom) * 32.0f);
    int vz = (int)floorf(((z - pmin) / denom) * 32.0f);

    if ((unsigned)vx < 32u && (unsigned)vy < 32u && (unsigned)vz < 32u) {
        int b   = p / npb;
        int bin = b * NVOX + vx * (GRIDR * GRIDR) + vy * GRIDR + vz;
        g_gidx[p] = bin;
        g_rank[p] = atomicAdd(&g_cnt[bin], 1);
    } else {
        g_gidx[p] = -1;   // JAX drops OOB scatter indices
    }
}

// K2: per-256-bin-block exclusive scan (shfl-based) + atomic base allocation.
// Segment ORDER in g_plist is arbitrary (execution order of blocks) but
// segments are disjoint & sized right — the gather's max is placement-invariant.
__global__ void scan_block_kernel() {
    __shared__ int wsum[8];
    int i = blockIdx.x * 256 + threadIdx.x;
    int lane = threadIdx.x & 31;
    int w    = threadIdx.x >> 5;
    int v = g_cnt[i];
    int x = v;
    #pragma unroll
    for (int d = 1; d < 32; d <<= 1) {
        int t = __shfl_up_sync(0xFFFFFFFFu, x, d);
        if (lane >= d) x += t;
    }
    if (lane == 31) wsum[w] = x;
    __syncthreads();
    if (w == 0 && lane < 8) {
        int y = wsum[lane];
        #pragma unroll
        for (int d = 1; d < 8; d <<= 1) {
            int t = __shfl_up_sync(0xFFu, y, d);
            if (lane >= d) y += t;
        }
        wsum[lane] = y;
    }
    __syncthreads();
    int off = (w > 0) ? wsum[w - 1] : 0;
    g_partoff[i] = off + x - v;                    // exclusive within block
    if (threadIdx.x == 255)
        g_blockbase[blockIdx.x] = atomicAdd(&g_cursor, off + x);
}

// K3: scatter point ids into per-bin contiguous segments.
// Also resets min/max seeds + cursor (their consumers already ran).
__global__ void scatter_ids_kernel(int np) {
    int p = blockIdx.x * blockDim.x + threadIdx.x;
    if (p == 0) {
        g_min_bits = 0x7f800000;
        g_max_bits = 0xff800000;
        g_cursor   = 0;
    }
    if (p >= np) return;
    int bin = g_gidx[p];
    if (bin < 0) return;
    int slot = g_partoff[bin] + g_blockbase[bin >> 8] + g_rank[p];
    g_plist[slot] = p;
}

// K4: per-voxel gather-max. One WARP per voxel: 4 subs x 8 lanes; each lane
// owns float4 chunks c and c+8 of the 16 per point. 8-pt unroll -> 16 float4
// loads in flight per thread. Quarter-warp reads a point's contiguous 2x128B.
// Combine subs via shfl_xor(8) + shfl_xor(16). acc starts at 0 == reference
// zero-init max. Also re-zeroes g_cnt for the next call.
__global__ void gather_kernel(const float4* __restrict__ feat,
                              float4* __restrict__ out) {
    int t = blockIdx.x * blockDim.x + threadIdx.x;   // NBINS*32 threads
    int v    = t >> 5;
    int lane = t & 31;
    int s    = lane >> 3;       // sub 0..3
    int c    = lane & 7;        // chunk pair: c and c+8
    int k = g_cnt[v];
    float4 a0 = make_float4(0.f, 0.f, 0.f, 0.f);
    float4 a1 = make_float4(0.f, 0.f, 0.f, 0.f);
    if (k > 0) {
        int base = g_partoff[v] + g_blockbase[v >> 8];
        int i = s;
        // 8 points per sub per iteration (stride 4 across subs)
        for (; i + 28 < k; i += 32) {
            int p0 = g_plist[base + i];
            int p1 = g_plist[base + i +  4];
            int p2 = g_plist[base + i +  8];
            int p3 = g_plist[base + i + 12];
            int p4 = g_plist[base + i + 16];
            int p5 = g_plist[base + i + 20];
            int p6 = g_plist[base + i + 24];
            int p7 = g_plist[base + i + 28];
            float4 f00 = feat[p0 * 16 + c], f01 = feat[p0 * 16 + c + 8];
            float4 f10 = feat[p1 * 16 + c], f11 = feat[p1 * 16 + c + 8];
            float4 f20 = feat[p2 * 16 + c], f21 = feat[p2 * 16 + c + 8];
            float4 f30 = feat[p3 * 16 + c], f31 = feat[p3 * 16 + c + 8];
            float4 f40 = feat[p4 * 16 + c], f41 = feat[p4 * 16 + c + 8];
            float4 f50 = feat[p5 * 16 + c], f51 = feat[p5 * 16 + c + 8];
            float4 f60 = feat[p6 * 16 + c], f61 = feat[p6 * 16 + c + 8];
            float4 f70 = feat[p7 * 16 + c], f71 = feat[p7 * 16 + c + 8];
            fmax4(f00, f10); fmax4(f20, f30); fmax4(f40, f50); fmax4(f60, f70);
            fmax4(f01, f11); fmax4(f21, f31); fmax4(f41, f51); fmax4(f61, f71);
            fmax4(f00, f20); fmax4(f40, f60);
            fmax4(f01, f21); fmax4(f41, f61);
            fmax4(f00, f40); fmax4(f01, f41);
            fmax4(a0, f00);  fmax4(a1, f01);
        }
        for (; i < k; i += 4) {
            int p = g_plist[base + i];
            float4 f0 = feat[p * 16 + c];
            float4 f1 = feat[p * 16 + c + 8];
            fmax4(a0, f0);
            fmax4(a1, f1);
        }
    }
    // combine the 4 subs (all 32 lanes converged here)
    #pragma unroll
    for (int o = 8; o <= 16; o <<= 1) {
        a0.x = fmaxf(a0.x, __shfl_xor_sync(0xFFFFFFFFu, a0.x, o));
        a0.y = fmaxf(a0.y, __shfl_xor_sync(0xFFFFFFFFu, a0.y, o));
        a0.z = fmaxf(a0.z, __shfl_xor_sync(0xFFFFFFFFu, a0.z, o));
        a0.w = fmaxf(a0.w, __shfl_xor_sync(0xFFFFFFFFu, a0.w, o));
        a1.x = fmaxf(a1.x, __shfl_xor_sync(0xFFFFFFFFu, a1.x, o));
        a1.y = fmaxf(a1.y, __shfl_xor_sync(0xFFFFFFFFu, a1.y, o));
        a1.z = fmaxf(a1.z, __shfl_xor_sync(0xFFFFFFFFu, a1.z, o));
        a1.w = fmaxf(a1.w, __shfl_xor_sync(0xFFFFFFFFu, a1.w, o));
    }
    if (lane < 8) {
        out[v * 16 + c]     = a0;   // [bin][16] float4s == [B,32^3,64] f32
        out[v * 16 + c + 8] = a1;
    }
    if (lane == 0) g_cnt[v] = 0;    // reset for next call
}

extern "C" void kernel_launch(void* const* d_in, const int* in_sizes, int n_in,
                              void* d_out, int out_size) {
    const float* points   = (const float*)d_in[0];   // B*N*3
    const float* features = (const float*)d_in[1];   // B*N*64

    int np  = in_sizes[0] / 3;          // total points = B*N
    int npb = np / NBATCH;              // points per batch

    {
        int n4 = in_sizes[0] / 4;       // 1.2M floats -> 300k float4
        minmax_kernel<<<1024, 256>>>((const float4*)points, n4);
    }
    gidx_kernel<<<(np + 255) / 256, 256>>>(points, np, npb);
    scan_block_kernel<<<NBINS / 256, 256>>>();
    scatter_ids_kernel<<<(np + 255) / 256, 256>>>(np);
    {
        long long total = (long long)NBINS * 32;    // one warp per voxel
        gather_kernel<<<(int)(total / 256), 256>>>((const float4*)features,
                                                   (float4*)d_out);
    }
}